// round 13
// baseline (speedup 1.0000x reference)
#include <cuda_runtime.h>
#include <cuda_bf16.h>
#include <cstdint>

#define LSEQ 384
#define DSEQ 256
#define H    32
#define P    128

// ---------------------------------------------------------------------------
// scratch (__device__ globals; allocation-free rule)
// ---------------------------------------------------------------------------
__device__ float g_s1[LSEQ * H];
__device__ float g_s2[LSEQ * H];

// A fragments (hi/lo planes), m16n8k16 layout
__device__ uint4 g_Abh[3 * 512],  g_Abl[3 * 512];   // S2  A-frags, per j-tile
__device__ uint4 g_As1h[3 * 512], g_As1l[3 * 512];  // s1  A-frags, per i-tile
// T B-fragments, interleaved {b0h, b1h, b0l, b1l} per slot, 1024 slots (16KB)/i
__device__ uint4 g_Tb[(size_t)LSEQ * 1024];

// ---------------------------------------------------------------------------
// helpers
// ---------------------------------------------------------------------------
__device__ __forceinline__ uint32_t smem_u32(const void* p) {
    uint32_t a;
    asm("{ .reg .u64 t; cvta.to.shared.u64 t, %1; cvt.u32.u64 %0, t; }"
        : "=r"(a) : "l"(p));
    return a;
}
__device__ __forceinline__ void cp16(uint32_t dst, const void* src) {
    asm volatile("cp.async.cg.shared.global [%0], [%1], 16;"
                 :: "r"(dst), "l"(src));
}
#define CP_COMMIT() asm volatile("cp.async.commit_group;" ::: "memory")

// bf16 split: h = packed bf16(x0)|bf16(x1), l = packed residuals
__device__ __forceinline__ void split_pair(float x0, float x1,
                                           uint32_t& h, uint32_t& l) {
    asm("cvt.rn.bf16x2.f32 %0, %1, %2;" : "=r"(h) : "f"(x1), "f"(x0));
    float r0 = x0 - __uint_as_float(h << 16);
    float r1 = x1 - __uint_as_float(h & 0xffff0000u);
    asm("cvt.rn.bf16x2.f32 %0, %1, %2;" : "=r"(l) : "f"(r1), "f"(r0));
}

__device__ __forceinline__ void mma_bf16(float* d, const uint4& a, const uint2& b) {
    asm("mma.sync.aligned.m16n8k16.row.col.f32.bf16.bf16.f32 "
        "{%0,%1,%2,%3},{%4,%5,%6,%7},{%8,%9},{%0,%1,%2,%3};"
        : "+f"(d[0]), "+f"(d[1]), "+f"(d[2]), "+f"(d[3])
        : "r"(a.x), "r"(a.y), "r"(a.z), "r"(a.w), "r"(b.x), "r"(b.y));
}

// 128 x (NT*32) (K=32) bf16x3 mainloop (tgemm only); B interleaved slots
template<int NT>
__device__ __forceinline__ void gemm_compute(
    const uint4* sAH, const uint4* sAL, const uint4* sB,
    int wm, int wn, int lane, float acc[4][NT][4])
{
    #pragma unroll
    for (int kt = 0; kt < 2; kt++) {
        uint2 bh[NT], bl[NT];
        #pragma unroll
        for (int nt = 0; nt < NT; nt++) {
            uint4 v = sB[(kt * 4 * NT + wn * NT + nt) * 32 + lane];
            bh[nt] = make_uint2(v.x, v.y);
            bl[nt] = make_uint2(v.z, v.w);
        }
        #pragma unroll
        for (int mt = 0; mt < 4; mt++) {
            int ai = (kt * 8 + wm * 4 + mt) * 32 + lane;
            uint4 ah = sAH[ai], al = sAL[ai];
            #pragma unroll
            for (int nt = 0; nt < NT; nt++) {
                mma_bf16(acc[mt][nt], ah, bh[nt]);
                mma_bf16(acc[mt][nt], ah, bl[nt]);
                mma_bf16(acc[mt][nt], al, bh[nt]);
            }
        }
    }
}

// Fragment slot for pair-GEMM B, PERMUTED p mapping (matches pair epilogue):
__device__ __forceinline__ int bfrag_slot(int p, int f0) {
    int g = p & 31, wnp = p >> 5;
    int ntp = ((g >> 4) & 1) * 2 + ((g >> 1) & 1);
    int j   = ((g >> 2) & 3) * 2 + (g & 1);
    return ((f0 >> 4) * 16 + wnp * 4 + ntp) * 32 + j * 4 + ((f0 >> 1) & 3);
}

// ---------------------------------------------------------------------------
// lnproj: fused LayerNorm + both 256->64 projections as a smem-tiled GEMM.
// Grid 6: CTA handles 64 rows; weights staged ONCE per CTA (not per row).
// Ws row stride 260 floats (multiple of 4 -> float4-aligned rows).
// ---------------------------------------------------------------------------
#define WSTRIDE 260
#define LNP_SMEM ((64 * WSTRIDE + 64 * 256) * 4)

__global__ __launch_bounds__(256) void lnproj_kernel(
    const float* __restrict__ seq,
    const float* __restrict__ gamma, const float* __restrict__ beta,
    const float* __restrict__ w1, const float* __restrict__ b1,
    const float* __restrict__ w2, const float* __restrict__ b2)
{
    extern __shared__ float sm[];
    float* Ws = sm;                    // [64][WSTRIDE] (w1 rows 0-31, w2 32-63)
    float* Xs = sm + 64 * WSTRIDE;     // [64][256] LayerNorm'd rows
    int tid = threadIdx.x, lane = tid & 31, wid = tid >> 5;
    int r0 = blockIdx.x * 64;

    #pragma unroll
    for (int n = 0; n < 16; n++) {
        int p = tid + n * 256;                // 0..4095 float4s
        int h = p >> 6, k4 = (p & 63) * 4;
        const float* src = (h < 32) ? (w1 + h * DSEQ) : (w2 + (h - 32) * DSEQ);
        float4 v = __ldg((const float4*)(src + k4));
        *(float4*)(Ws + h * WSTRIDE + k4) = v;
    }

    // LayerNorm: one warp per row, 8 rounds
    float4 ga0 = __ldg((const float4*)gamma + lane);
    float4 ga1 = __ldg((const float4*)gamma + lane + 32);
    float4 be0 = __ldg((const float4*)beta + lane);
    float4 be1 = __ldg((const float4*)beta + lane + 32);
    for (int rr = 0; rr < 8; rr++) {
        int row = rr * 8 + wid;
        const float4* srow = (const float4*)(seq + (size_t)(r0 + row) * DSEQ);
        float4 v0 = __ldg(srow + lane);
        float4 v1 = __ldg(srow + lane + 32);
        float s = v0.x + v0.y + v0.z + v0.w + v1.x + v1.y + v1.z + v1.w;
        float q = v0.x*v0.x + v0.y*v0.y + v0.z*v0.z + v0.w*v0.w
                + v1.x*v1.x + v1.y*v1.y + v1.z*v1.z + v1.w*v1.w;
        #pragma unroll
        for (int o = 16; o; o >>= 1) {
            s += __shfl_xor_sync(0xffffffffu, s, o);
            q += __shfl_xor_sync(0xffffffffu, q, o);
        }
        float mu   = s * (1.f / DSEQ);
        float var  = q * (1.f / DSEQ) - mu * mu;
        float rstd = rsqrtf(var + 1e-5f);
        float4 n0, n1;
        n0.x = (v0.x - mu) * rstd * ga0.x + be0.x;
        n0.y = (v0.y - mu) * rstd * ga0.y + be0.y;
        n0.z = (v0.z - mu) * rstd * ga0.z + be0.z;
        n0.w = (v0.w - mu) * rstd * ga0.w + be0.w;
        n1.x = (v1.x - mu) * rstd * ga1.x + be1.x;
        n1.y = (v1.y - mu) * rstd * ga1.y + be1.y;
        n1.z = (v1.z - mu) * rstd * ga1.z + be1.z;
        n1.w = (v1.w - mu) * rstd * ga1.w + be1.w;
        ((float4*)(Xs + row * 256))[lane]      = n0;
        ((float4*)(Xs + row * 256))[lane + 32] = n1;
    }
    __syncthreads();

    // GEMM: rows rloc..rloc+3, cols h0 + {0,16,32,48}
    int h0 = tid & 15, rloc = (tid >> 4) * 4;
    float acc[4][4];
    #pragma unroll
    for (int a = 0; a < 4; a++)
        #pragma unroll
        for (int b = 0; b < 4; b++) acc[a][b] = 0.f;

    #pragma unroll 8
    for (int kp = 0; kp < 128; kp++) {
        float2 xv[4], wv[4];
        #pragma unroll
        for (int rr = 0; rr < 4; rr++)
            xv[rr] = *(const float2*)(Xs + (rloc + rr) * 256 + kp * 2);
        #pragma unroll
        for (int hh = 0; hh < 4; hh++)
            wv[hh] = *(const float2*)(Ws + (h0 + hh * 16) * WSTRIDE + kp * 2);
        #pragma unroll
        for (int rr = 0; rr < 4; rr++)
            #pragma unroll
            for (int hh = 0; hh < 4; hh++)
                acc[rr][hh] += xv[rr].x * wv[hh].x + xv[rr].y * wv[hh].y;
    }

    #pragma unroll
    for (int hh = 0; hh < 4; hh++) {
        int h = h0 + hh * 16;
        float bb = (h < 32) ? __ldg(b1 + h) : __ldg(b2 + h - 32);
        #pragma unroll
        for (int rr = 0; rr < 4; rr++) {
            float v = acc[rr][hh] + bb;
            int i = r0 + rloc + rr;
            if (h < 32) g_s1[i * H + h] = v;
            else        g_s2[i * H + h - 32] = v;
        }
    }
}

// ---------------------------------------------------------------------------
// asplit: pre-build A fragments (hi/lo bf16) for S2 (first half) and s1 (second)
// ---------------------------------------------------------------------------
__global__ __launch_bounds__(256) void asplit_kernel()
{
    int gid = blockIdx.x * 256 + threadIdx.x;      // 0..3071
    int sel = gid >= 1536;
    int idx = sel ? gid - 1536 : gid;
    const float* src = sel ? g_s1 : g_s2;
    uint4* dh = sel ? g_As1h : g_Abh;
    uint4* dl = sel ? g_As1l : g_Abl;

    int lane = idx & 31, rest = idx >> 5;
    int mt = rest & 7, kt = (rest >> 3) & 1, tile = rest >> 4;
    int r = tile * 128 + mt * 16 + (lane >> 2);
    int c = kt * 16 + (lane & 3) * 2;

    float2 v00 = *(const float2*)(src + r * H + c);
    float2 v10 = *(const float2*)(src + (r + 8) * H + c);
    float2 v01 = *(const float2*)(src + r * H + c + 8);
    float2 v11 = *(const float2*)(src + (r + 8) * H + c + 8);
    uint4 hi, lo;
    split_pair(v00.x, v00.y, hi.x, lo.x);
    split_pair(v10.x, v10.y, hi.y, lo.y);
    split_pair(v01.x, v01.y, hi.z, lo.z);
    split_pair(v11.x, v11.y, hi.w, lo.w);
    dh[idx] = hi; dl[idx] = lo;
}

// ---------------------------------------------------------------------------
// tgemm: T[i, n] = sum_d s1[i,d]*w3[n>>5, d*32+(n&31)]  (M=384, N=4096, K=32)
// ---------------------------------------------------------------------------
__global__ __launch_bounds__(256) void tgemm_kernel(const float* __restrict__ w3)
{
    __shared__ float ws[2048];
    __shared__ uint4 sAH[512], sAL[512];
    __shared__ uint4 sB[512];
    int tid = threadIdx.x, lane = tid & 31;
    int itile = blockIdx.x, ntile = blockIdx.y;

    const float4* wsrc = (const float4*)(w3 + (size_t)ntile * 2 * (H * H));
    float4* wdst = (float4*)ws;
    wdst[tid]       = __ldg(wsrc + tid);
    wdst[tid + 256] = __ldg(wsrc + tid + 256);

    sAH[tid]       = g_As1h[itile * 512 + tid];
    sAH[tid + 256] = g_As1h[itile * 512 + tid + 256];
    sAL[tid]       = g_As1l[itile * 512 + tid];
    sAL[tid + 256] = g_As1l[itile * 512 + tid + 256];
    __syncthreads();

    #pragma unroll
    for (int k = 0; k < 2; k++) {
        int t = tid + k * 256;
        int la = t & 31, nt8 = (t >> 5) & 7, kt = t >> 8;
        int nl = nt8 * 8 + (la >> 2);
        int pl = nl >> 5, f = nl & 31;
        int d0 = kt * 16 + (la & 3) * 2;
        const float* wp = ws + pl * 1024;
        float v00 = wp[d0 * H + f];
        float v01 = wp[(d0 + 1) * H + f];
        float v10 = wp[(d0 + 8) * H + f];
        float v11 = wp[(d0 + 9) * H + f];
        uint32_t b0h, b0l, b1h, b1l;
        split_pair(v00, v01, b0h, b0l);
        split_pair(v10, v11, b1h, b1l);
        sB[t] = make_uint4(b0h, b1h, b0l, b1l);
    }

    float acc[4][2][4];
    #pragma unroll
    for (int a = 0; a < 4; a++)
        #pragma unroll
        for (int b = 0; b < 2; b++)
            #pragma unroll
            for (int c = 0; c < 4; c++) acc[a][b][c] = 0.f;
    __syncthreads();

    int wid = tid >> 5, wm = wid >> 2, wn = wid & 3;
    gemm_compute<2>(sAH, sAL, sB, wm, wn, lane, acc);

    int n_base = ntile * 64 + wn * 16 + (lane & 3) * 2;
    int pg = n_base >> 5, f0 = n_base & 31;
    int slot = bfrag_slot(pg, f0);
    #pragma unroll
    for (int mt = 0; mt < 4; mt++) {
        int i = itile * 128 + wm * 64 + mt * 16 + (lane >> 2);
        uint32_t b0h, b0l, b1h, b1l;
        split_pair(acc[mt][0][0], acc[mt][0][1], b0h, b0l);
        split_pair(acc[mt][1][0], acc[mt][1][1], b1h, b1l);
        g_Tb[(size_t)i * 1024 + slot] = make_uint4(b0h, b1h, b0l, b1l);
        split_pair(acc[mt][0][2], acc[mt][0][3], b0h, b0l);
        split_pair(acc[mt][1][2], acc[mt][1][3], b1h, b1l);
        g_Tb[(size_t)(i + 8) * 1024 + slot] = make_uint4(b0h, b1h, b0l, b1l);
    }
}

// ---------------------------------------------------------------------------
// pair: pair[i,j,p] = b3[p] + sum_f S2[j,f]*T[i,p,f].
// CTA = (i-triple, jtile): grid 128x3 = 384, 3 CTAs/SM (regs capped by
// per-mt accumulation: only 16 acc floats live; stores interleave with MMA).
// SMEM 64KB: B0/B1/B2 @ 0/16K/32K, A hi @ 48K, A lo @ 56K.
// ---------------------------------------------------------------------------
#define PAIR_SMEM 65536

__global__ __launch_bounds__(256, 3) void pair_kernel(
    const float* __restrict__ b3, float* __restrict__ out)
{
    extern __shared__ __align__(16) char ps[];
    int tid = threadIdx.x, lane = tid & 31, wid = tid >> 5;
    int wm = wid >> 2, wn = wid & 3, q = lane & 3;
    int iq = blockIdx.x, jt = blockIdx.y;
    int i0 = iq * 3;
    uint32_t sb = smem_u32(ps);

    // group 0: A frags (hi @48K, lo @56K) + B0
    cp16(sb + 49152 + tid * 16,         &g_Abh[jt * 512 + tid]);
    cp16(sb + 49152 + (tid+256) * 16,   &g_Abh[jt * 512 + tid + 256]);
    cp16(sb + 57344 + tid * 16,         &g_Abl[jt * 512 + tid]);
    cp16(sb + 57344 + (tid+256) * 16,   &g_Abl[jt * 512 + tid + 256]);
    #pragma unroll
    for (int it = 0; it < 3; it++) {
        uint32_t base = sb + it * 16384;
        const uint4* src = g_Tb + (size_t)(i0 + it) * 1024;
        cp16(base + tid * 16,           src + tid);
        cp16(base + (tid + 256) * 16,   src + tid + 256);
        cp16(base + (tid + 512) * 16,   src + tid + 512);
        cp16(base + (tid + 768) * 16,   src + tid + 768);
        CP_COMMIT();
    }

    float4 bvf0 = __ldg((const float4*)(b3 + wn * 32 + q * 4));
    float4 bvf1 = __ldg((const float4*)(b3 + wn * 32 + 16 + q * 4));

    const uint4* sAH = (const uint4*)(ps + 49152);
    const uint4* sAL = (const uint4*)(ps + 57344);

    #pragma unroll
    for (int it = 0; it < 3; it++) {
        if      (it == 0) asm volatile("cp.async.wait_group 2;" ::: "memory");
        else if (it == 1) asm volatile("cp.async.wait_group 1;" ::: "memory");
        else              asm volatile("cp.async.wait_group 0;" ::: "memory");
        __syncthreads();

        const uint4* sB = (const uint4*)(ps + it * 16384);
        uint4 B0[4], B1[4];
        #pragma unroll
        for (int nt = 0; nt < 4; nt++) {
            B0[nt] = sB[(wn * 4 + nt) * 32 + lane];
            B1[nt] = sB[(16 + wn * 4 + nt) * 32 + lane];
        }

        float* obase = out + (size_t)(i0 + it) * LSEQ * P;
        #pragma unroll
        for (int mt = 0; mt < 4; mt++) {
            uint4 ah0 = sAH[(wm * 4 + mt) * 32 + lane];
            uint4 al0 = sAL[(wm * 4 + mt) * 32 + lane];
            uint4 ah1 = sAH[(8 + wm * 4 + mt) * 32 + lane];
            uint4 al1 = sAL[(8 + wm * 4 + mt) * 32 + lane];

            float acc[4][4];
            acc[0][0] = bvf0.x; acc[0][1] = bvf0.y; acc[0][2] = bvf0.x; acc[0][3] = bvf0.y;
            acc[1][0] = bvf0.z; acc[1][1] = bvf0.w; acc[1][2] = bvf0.z; acc[1][3] = bvf0.w;
            acc[2][0] = bvf1.x; acc[2][1] = bvf1.y; acc[2][2] = bvf1.x; acc[2][3] = bvf1.y;
            acc[3][0] = bvf1.z; acc[3][1] = bvf1.w; acc[3][2] = bvf1.z; acc[3][3] = bvf1.w;

            #pragma unroll
            for (int nt = 0; nt < 4; nt++) {
                uint2 bh = make_uint2(B0[nt].x, B0[nt].y);
                uint2 bl = make_uint2(B0[nt].z, B0[nt].w);
                mma_bf16(acc[nt], ah0, bh);
                mma_bf16(acc[nt], ah0, bl);
                mma_bf16(acc[nt], al0, bh);
            }
            #pragma unroll
            for (int nt = 0; nt < 4; nt++) {
                uint2 bh = make_uint2(B1[nt].x, B1[nt].y);
                uint2 bl = make_uint2(B1[nt].z, B1[nt].w);
                mma_bf16(acc[nt], ah1, bh);
                mma_bf16(acc[nt], ah1, bl);
                mma_bf16(acc[nt], al1, bh);
            }

            int row = jt * 128 + wm * 64 + mt * 16 + (lane >> 2);
            float* o0 = obase + (size_t)row * P + wn * 32 + q * 4;
            *(float4*)(o0)            = make_float4(acc[0][0], acc[0][1], acc[1][0], acc[1][1]);
            *(float4*)(o0 + 16)       = make_float4(acc[2][0], acc[2][1], acc[3][0], acc[3][1]);
            *(float4*)(o0 + 8 * P)      = make_float4(acc[0][2], acc[0][3], acc[1][2], acc[1][3]);
            *(float4*)(o0 + 8 * P + 16) = make_float4(acc[2][2], acc[2][3], acc[3][2], acc[3][3]);
        }
    }
}

extern "C" void kernel_launch(void* const* d_in, const int* in_sizes, int n_in,
                              void* d_out, int out_size)
{
    const float* seq   = (const float*)d_in[0];
    const float* gamma = (const float*)d_in[1];
    const float* beta  = (const float*)d_in[2];
    const float* w1    = (const float*)d_in[3];
    const float* b1    = (const float*)d_in[4];
    const float* w2    = (const float*)d_in[5];
    const float* b2    = (const float*)d_in[6];
    const float* w3    = (const float*)d_in[7];
    const float* b3    = (const float*)d_in[8];

    cudaFuncSetAttribute(lnproj_kernel,
                         cudaFuncAttributeMaxDynamicSharedMemorySize, LNP_SMEM);
    cudaFuncSetAttribute(pair_kernel,
                         cudaFuncAttributeMaxDynamicSharedMemorySize, PAIR_SMEM);

    lnproj_kernel<<<6, 256, LNP_SMEM>>>(seq, gamma, beta, w1, b1, w2, b2);
    asplit_kernel<<<12, 256>>>();
    tgemm_kernel<<<dim3(3, 64), 256>>>(w3);
    pair_kernel<<<dim3(128, 3), 256, PAIR_SMEM>>>(b3, (float*)d_out);
}

// round 14
// speedup vs baseline: 1.2114x; 1.2114x over previous
#include <cuda_runtime.h>
#include <cuda_bf16.h>
#include <cstdint>

#define LSEQ 384
#define DSEQ 256
#define H    32
#define P    128

// ---------------------------------------------------------------------------
// scratch (__device__ globals; allocation-free rule)
// ---------------------------------------------------------------------------
// A fragments (hi/lo planes), m16n8k16 layout
__device__ uint4 g_Abh[3 * 512],  g_Abl[3 * 512];   // S2  A-frags, per j-tile
__device__ uint4 g_As1h[3 * 512], g_As1l[3 * 512];  // s1  A-frags, per i-tile
// T B-fragments, interleaved {b0h, b1h, b0l, b1l} per slot, 1024 slots (16KB)/i
__device__ uint4 g_Tb[(size_t)LSEQ * 1024];

// ---------------------------------------------------------------------------
// helpers
// ---------------------------------------------------------------------------
__device__ __forceinline__ uint32_t smem_u32(const void* p) {
    uint32_t a;
    asm("{ .reg .u64 t; cvta.to.shared.u64 t, %1; cvt.u32.u64 %0, t; }"
        : "=r"(a) : "l"(p));
    return a;
}
__device__ __forceinline__ void cp16(uint32_t dst, const void* src) {
    asm volatile("cp.async.cg.shared.global [%0], [%1], 16;"
                 :: "r"(dst), "l"(src));
}
#define CP_COMMIT() asm volatile("cp.async.commit_group;" ::: "memory")

// bf16 split: h = packed bf16(x0)|bf16(x1), l = packed residuals
__device__ __forceinline__ void split_pair(float x0, float x1,
                                           uint32_t& h, uint32_t& l) {
    asm("cvt.rn.bf16x2.f32 %0, %1, %2;" : "=r"(h) : "f"(x1), "f"(x0));
    float r0 = x0 - __uint_as_float(h << 16);
    float r1 = x1 - __uint_as_float(h & 0xffff0000u);
    asm("cvt.rn.bf16x2.f32 %0, %1, %2;" : "=r"(l) : "f"(r1), "f"(r0));
}

__device__ __forceinline__ void mma_bf16(float* d, const uint4& a, const uint2& b) {
    asm("mma.sync.aligned.m16n8k16.row.col.f32.bf16.bf16.f32 "
        "{%0,%1,%2,%3},{%4,%5,%6,%7},{%8,%9},{%0,%1,%2,%3};"
        : "+f"(d[0]), "+f"(d[1]), "+f"(d[2]), "+f"(d[3])
        : "r"(a.x), "r"(a.y), "r"(a.z), "r"(a.w), "r"(b.x), "r"(b.y));
}

// 128 x (NT*32) (K=32) bf16x3 mainloop; B interleaved slots
template<int NT>
__device__ __forceinline__ void gemm_compute(
    const uint4* sAH, const uint4* sAL, const uint4* sB,
    int wm, int wn, int lane, float acc[4][NT][4])
{
    #pragma unroll
    for (int kt = 0; kt < 2; kt++) {
        uint2 bh[NT], bl[NT];
        #pragma unroll
        for (int nt = 0; nt < NT; nt++) {
            uint4 v = sB[(kt * 4 * NT + wn * NT + nt) * 32 + lane];
            bh[nt] = make_uint2(v.x, v.y);
            bl[nt] = make_uint2(v.z, v.w);
        }
        #pragma unroll
        for (int mt = 0; mt < 4; mt++) {
            int ai = (kt * 8 + wm * 4 + mt) * 32 + lane;
            uint4 ah = sAH[ai], al = sAL[ai];
            #pragma unroll
            for (int nt = 0; nt < NT; nt++) {
                mma_bf16(acc[mt][nt], ah, bh[nt]);
                mma_bf16(acc[mt][nt], ah, bl[nt]);
                mma_bf16(acc[mt][nt], al, bh[nt]);
            }
        }
    }
}

// Fragment slot for pair-GEMM B, PERMUTED p mapping (matches pair epilogue):
__device__ __forceinline__ int bfrag_slot(int p, int f0) {
    int g = p & 31, wnp = p >> 5;
    int ntp = ((g >> 4) & 1) * 2 + ((g >> 1) & 1);
    int j   = ((g >> 2) & 3) * 2 + (g & 1);
    return ((f0 >> 4) * 16 + wnp * 4 + ntp) * 32 + j * 4 + ((f0 >> 1) & 3);
}

// ---------------------------------------------------------------------------
// lnproj: fused LayerNorm + both 256->32 projections + A-fragment build.
// Grid 24, CTA = 16 aligned rows = (tile = blk>>3, mt = blk&7): every A-frag
// item of (tile, mt) touches only rows mt*16+r and +8 -> fully CTA-local.
// Deletes the separate asplit kernel and the g_s1/g_s2 global round trip.
// ---------------------------------------------------------------------------
#define WSTRIDE 260
#define LNP_SMEM (64 * WSTRIDE * 4 + 16 * 256 * 4)   // 82944 B

__global__ __launch_bounds__(256) void lnproj_kernel(
    const float* __restrict__ seq,
    const float* __restrict__ gamma, const float* __restrict__ beta,
    const float* __restrict__ w1, const float* __restrict__ b1,
    const float* __restrict__ w2, const float* __restrict__ b2)
{
    extern __shared__ float sm[];
    float* Ws = sm;                    // [64][WSTRIDE] (w1 rows 0-31, w2 32-63)
    float* Xs = sm + 64 * WSTRIDE;     // [16][256] LayerNorm'd rows
    float* S  = sm;                    // [16][68] projections; overlays Ws later
    int tid = threadIdx.x, lane = tid & 31, wid = tid >> 5;
    int blk = blockIdx.x;
    int r0 = blk * 16;

    // stage all 64 weight rows (float4-aligned stride 260)
    #pragma unroll
    for (int n = 0; n < 16; n++) {
        int p = tid + n * 256;                // 0..4095 float4s
        int h = p >> 6, k4 = (p & 63) * 4;
        const float* src = (h < 32) ? (w1 + h * DSEQ) : (w2 + (h - 32) * DSEQ);
        *(float4*)(Ws + h * WSTRIDE + k4) = __ldg((const float4*)(src + k4));
    }

    // LayerNorm: one warp per row, 2 rounds
    float4 ga0 = __ldg((const float4*)gamma + lane);
    float4 ga1 = __ldg((const float4*)gamma + lane + 32);
    float4 be0 = __ldg((const float4*)beta + lane);
    float4 be1 = __ldg((const float4*)beta + lane + 32);
    #pragma unroll
    for (int rr = 0; rr < 2; rr++) {
        int row = rr * 8 + wid;
        const float4* srow = (const float4*)(seq + (size_t)(r0 + row) * DSEQ);
        float4 v0 = __ldg(srow + lane);
        float4 v1 = __ldg(srow + lane + 32);
        float s = v0.x + v0.y + v0.z + v0.w + v1.x + v1.y + v1.z + v1.w;
        float q = v0.x*v0.x + v0.y*v0.y + v0.z*v0.z + v0.w*v0.w
                + v1.x*v1.x + v1.y*v1.y + v1.z*v1.z + v1.w*v1.w;
        #pragma unroll
        for (int o = 16; o; o >>= 1) {
            s += __shfl_xor_sync(0xffffffffu, s, o);
            q += __shfl_xor_sync(0xffffffffu, q, o);
        }
        float mu   = s * (1.f / DSEQ);
        float var  = q * (1.f / DSEQ) - mu * mu;
        float rstd = rsqrtf(var + 1e-5f);
        float4 n0, n1;
        n0.x = (v0.x - mu) * rstd * ga0.x + be0.x;
        n0.y = (v0.y - mu) * rstd * ga0.y + be0.y;
        n0.z = (v0.z - mu) * rstd * ga0.z + be0.z;
        n0.w = (v0.w - mu) * rstd * ga0.w + be0.w;
        n1.x = (v1.x - mu) * rstd * ga1.x + be1.x;
        n1.y = (v1.y - mu) * rstd * ga1.y + be1.y;
        n1.z = (v1.z - mu) * rstd * ga1.z + be1.z;
        n1.w = (v1.w - mu) * rstd * ga1.w + be1.w;
        ((float4*)(Xs + row * 256))[lane]      = n0;
        ((float4*)(Xs + row * 256))[lane + 32] = n1;
    }
    __syncthreads();

    // projection GEMM: thread = (row = tid>>4, h = (tid&15) + {0,16,32,48})
    int h0 = tid & 15, row = tid >> 4;
    float acc[4] = {0.f, 0.f, 0.f, 0.f};
    #pragma unroll 8
    for (int kp = 0; kp < 128; kp++) {
        float2 xv = *(const float2*)(Xs + row * 256 + kp * 2);
        #pragma unroll
        for (int hh = 0; hh < 4; hh++) {
            float2 wv = *(const float2*)(Ws + (h0 + hh * 16) * WSTRIDE + kp * 2);
            acc[hh] += xv.x * wv.x + xv.y * wv.y;
        }
    }
    __syncthreads();    // all Ws reads complete before S overlays it

    #pragma unroll
    for (int hh = 0; hh < 4; hh++) {
        int h = h0 + hh * 16;
        float bb = (h < 32) ? __ldg(b1 + h) : __ldg(b2 + h - 32);
        S[row * 68 + h] = acc[hh] + bb;     // s1 in cols 0-31, s2 in 32-63
    }
    __syncthreads();

    // A-fragment build for this CTA's (tile, mt): 128 items (2 mats x 2 kt x 32)
    if (tid < 128) {
        int mat = tid >> 6;                 // 0: s2 -> g_Ab*, 1: s1 -> g_As1*
        int kt  = (tid >> 5) & 1, la = tid & 31;
        int tile = blk >> 3, mt = blk & 7;
        int idx = tile * 512 + kt * 256 + mt * 32 + la;
        int lr = la >> 2;
        int c  = kt * 16 + (la & 3) * 2;
        int cs = mat ? c : (32 + c);
        float2 v00 = *(const float2*)(S + lr * 68 + cs);
        float2 v10 = *(const float2*)(S + (lr + 8) * 68 + cs);
        float2 v01 = *(const float2*)(S + lr * 68 + cs + 8);
        float2 v11 = *(const float2*)(S + (lr + 8) * 68 + cs + 8);
        uint4 hi, lo;
        split_pair(v00.x, v00.y, hi.x, lo.x);
        split_pair(v10.x, v10.y, hi.y, lo.y);
        split_pair(v01.x, v01.y, hi.z, lo.z);
        split_pair(v11.x, v11.y, hi.w, lo.w);
        if (mat) { g_As1h[idx] = hi; g_As1l[idx] = lo; }
        else     { g_Abh[idx]  = hi; g_Abl[idx]  = lo; }
    }
}

// ---------------------------------------------------------------------------
// tgemm: T[i, n] = sum_d s1[i,d]*w3[n>>5, d*32+(n&31)]  (M=384, N=4096, K=32)
// ---------------------------------------------------------------------------
__global__ __launch_bounds__(256) void tgemm_kernel(const float* __restrict__ w3)
{
    __shared__ float ws[2048];
    __shared__ uint4 sAH[512], sAL[512];
    __shared__ uint4 sB[512];
    int tid = threadIdx.x, lane = tid & 31;
    int itile = blockIdx.x, ntile = blockIdx.y;

    const float4* wsrc = (const float4*)(w3 + (size_t)ntile * 2 * (H * H));
    float4* wdst = (float4*)ws;
    wdst[tid]       = __ldg(wsrc + tid);
    wdst[tid + 256] = __ldg(wsrc + tid + 256);

    sAH[tid]       = g_As1h[itile * 512 + tid];
    sAH[tid + 256] = g_As1h[itile * 512 + tid + 256];
    sAL[tid]       = g_As1l[itile * 512 + tid];
    sAL[tid + 256] = g_As1l[itile * 512 + tid + 256];
    __syncthreads();

    #pragma unroll
    for (int k = 0; k < 2; k++) {
        int t = tid + k * 256;
        int la = t & 31, nt8 = (t >> 5) & 7, kt = t >> 8;
        int nl = nt8 * 8 + (la >> 2);
        int pl = nl >> 5, f = nl & 31;
        int d0 = kt * 16 + (la & 3) * 2;
        const float* wp = ws + pl * 1024;
        float v00 = wp[d0 * H + f];
        float v01 = wp[(d0 + 1) * H + f];
        float v10 = wp[(d0 + 8) * H + f];
        float v11 = wp[(d0 + 9) * H + f];
        uint32_t b0h, b0l, b1h, b1l;
        split_pair(v00, v01, b0h, b0l);
        split_pair(v10, v11, b1h, b1l);
        sB[t] = make_uint4(b0h, b1h, b0l, b1l);
    }

    float acc[4][2][4];
    #pragma unroll
    for (int a = 0; a < 4; a++)
        #pragma unroll
        for (int b = 0; b < 2; b++)
            #pragma unroll
            for (int c = 0; c < 4; c++) acc[a][b][c] = 0.f;
    __syncthreads();

    int wid = tid >> 5, wm = wid >> 2, wn = wid & 3;
    gemm_compute<2>(sAH, sAL, sB, wm, wn, lane, acc);

    int n_base = ntile * 64 + wn * 16 + (lane & 3) * 2;
    int pg = n_base >> 5, f0 = n_base & 31;
    int slot = bfrag_slot(pg, f0);
    #pragma unroll
    for (int mt = 0; mt < 4; mt++) {
        int i = itile * 128 + wm * 64 + mt * 16 + (lane >> 2);
        uint32_t b0h, b0l, b1h, b1l;
        split_pair(acc[mt][0][0], acc[mt][0][1], b0h, b0l);
        split_pair(acc[mt][1][0], acc[mt][1][1], b1h, b1l);
        g_Tb[(size_t)i * 1024 + slot] = make_uint4(b0h, b1h, b0l, b1l);
        split_pair(acc[mt][0][2], acc[mt][0][3], b0h, b0l);
        split_pair(acc[mt][1][2], acc[mt][1][3], b1h, b1l);
        g_Tb[(size_t)(i + 8) * 1024 + slot] = make_uint4(b0h, b1h, b0l, b1l);
    }
}

// ---------------------------------------------------------------------------
// pair (R10 measured-best): CTA = (i-quad, jtile), grid 96x3 = 288,
// 2 CTAs/SM, cp.async streamed B tiles, permuted-p float4 stores.
// ---------------------------------------------------------------------------
#define PAIR_SMEM 81920

__global__ __launch_bounds__(256, 2) void pair_kernel(
    const float* __restrict__ b3, float* __restrict__ out)
{
    extern __shared__ __align__(16) char ps[];
    int tid = threadIdx.x, lane = tid & 31, wid = tid >> 5;
    int wm = wid >> 2, wn = wid & 3, q = lane & 3;
    int iq = blockIdx.x, jt = blockIdx.y;
    int i0 = iq * 4;
    uint32_t sb = smem_u32(ps);

    // A frags (16 KB @ 65536): hi then lo (in commit group 0)
    cp16(sb + 65536 + tid * 16,        &g_Abh[jt * 512 + tid]);
    cp16(sb + 65536 + (tid+256) * 16,  &g_Abh[jt * 512 + tid + 256]);
    cp16(sb + 73728 + tid * 16,        &g_Abl[jt * 512 + tid]);
    cp16(sb + 73728 + (tid+256) * 16,  &g_Abl[jt * 512 + tid + 256]);
    // B frags for 4 i's (16 KB each), one commit-group per i
    #pragma unroll
    for (int it = 0; it < 4; it++) {
        uint32_t base = sb + it * 16384;
        const uint4* src = g_Tb + (size_t)(i0 + it) * 1024;
        cp16(base + tid * 16,             src + tid);
        cp16(base + (tid + 256) * 16,     src + tid + 256);
        cp16(base + (tid + 512) * 16,     src + tid + 512);
        cp16(base + (tid + 768) * 16,     src + tid + 768);
        CP_COMMIT();
    }

    // bias, permuted layout: col = wn*32 + blk*16 + q*4 + {0..3}
    float4 bvf[2];
    bvf[0] = __ldg((const float4*)(b3 + wn * 32 + q * 4));
    bvf[1] = __ldg((const float4*)(b3 + wn * 32 + 16 + q * 4));

    const uint4* sAH = (const uint4*)(ps + 65536);
    const uint4* sAL = (const uint4*)(ps + 73728);

    #pragma unroll
    for (int it = 0; it < 4; it++) {
        if      (it == 0) asm volatile("cp.async.wait_group 3;" ::: "memory");
        else if (it == 1) asm volatile("cp.async.wait_group 2;" ::: "memory");
        else if (it == 2) asm volatile("cp.async.wait_group 1;" ::: "memory");
        else              asm volatile("cp.async.wait_group 0;" ::: "memory");
        __syncthreads();

        float acc[4][4][4];
        #pragma unroll
        for (int blk = 0; blk < 2; blk++)
            #pragma unroll
            for (int mt = 0; mt < 4; mt++) {
                acc[mt][blk*2][0]   = bvf[blk].x; acc[mt][blk*2][1]   = bvf[blk].y;
                acc[mt][blk*2+1][0] = bvf[blk].z; acc[mt][blk*2+1][1] = bvf[blk].w;
                acc[mt][blk*2][2]   = bvf[blk].x; acc[mt][blk*2][3]   = bvf[blk].y;
                acc[mt][blk*2+1][2] = bvf[blk].z; acc[mt][blk*2+1][3] = bvf[blk].w;
            }

        const uint4* sB = (const uint4*)(ps + it * 16384);
        gemm_compute<4>(sAH, sAL, sB, wm, wn, lane, acc);

        #pragma unroll
        for (int mt = 0; mt < 4; mt++) {
            int row = jt * 128 + wm * 64 + mt * 16 + (lane >> 2);
            float* o0 = out + ((size_t)(i0 + it) * LSEQ + row) * P + wn * 32 + q * 4;
            #pragma unroll
            for (int blk = 0; blk < 2; blk++) {
                *(float4*)(o0 + blk * 16) =
                    make_float4(acc[mt][blk*2][0], acc[mt][blk*2][1],
                                acc[mt][blk*2+1][0], acc[mt][blk*2+1][1]);
                *(float4*)(o0 + 8 * P + blk * 16) =
                    make_float4(acc[mt][blk*2][2], acc[mt][blk*2][3],
                                acc[mt][blk*2+1][2], acc[mt][blk*2+1][3]);
            }
        }
    }
}

extern "C" void kernel_launch(void* const* d_in, const int* in_sizes, int n_in,
                              void* d_out, int out_size)
{
    const float* seq   = (const float*)d_in[0];
    const float* gamma = (const float*)d_in[1];
    const float* beta  = (const float*)d_in[2];
    const float* w1    = (const float*)d_in[3];
    const float* b1    = (const float*)d_in[4];
    const float* w2    = (const float*)d_in[5];
    const float* b2    = (const float*)d_in[6];
    const float* w3    = (const float*)d_in[7];
    const float* b3    = (const float*)d_in[8];

    cudaFuncSetAttribute(lnproj_kernel,
                         cudaFuncAttributeMaxDynamicSharedMemorySize, LNP_SMEM);
    cudaFuncSetAttribute(pair_kernel,
                         cudaFuncAttributeMaxDynamicSharedMemorySize, PAIR_SMEM);

    lnproj_kernel<<<24, 256, LNP_SMEM>>>(seq, gamma, beta, w1, b1, w2, b2);
    tgemm_kernel<<<dim3(3, 64), 256>>>(w3);
    pair_kernel<<<dim3(96, 3), 256, PAIR_SMEM>>>(b3, (float*)d_out);
}